// round 1
// baseline (speedup 1.0000x reference)
#include <cuda_runtime.h>
#include <cuda_bf16.h>
#include <stdint.h>

#define BUCKET_SIZE 512
#define G 444          // blocks for pass1/pass3 (3 per SM on 148 SMs)
#define BLK 512        // threads per block (16 warps)
#define MAXNB 8192     // max buckets supported (actual: 7813)

// Static scratch: per-block, per-bucket histogram / exclusive offsets.
// 444 * 8192 * 4B = 14.5 MB — fits in L2 (126 MB), so pass2/pass3 re-reads are cheap.
__device__ int g_hist[(size_t)G * MAXNB];

__device__ __forceinline__ unsigned bucket_of(float x, float y, float z,
                                              unsigned bid, unsigned hop,
                                              unsigned nb) {
    unsigned vx = (unsigned)(int)floorf(x);
    unsigned vy = (unsigned)(int)floorf(y);
    unsigned vz = (unsigned)(int)floorf(z);
    unsigned h = vx * 73856093u ^ vy * 19349663u ^ vz * 83492791u
               ^ bid * 2654435761u;
    h += hop;
    return h % nb;
}

// Pass 1: per-point bucket (written as f32 output) + per-block histogram.
__global__ __launch_bounds__(BLK) void psh_pass1(
    const float* __restrict__ coords, const int* __restrict__ seps,
    const int* __restrict__ hop_p, int n, int nB, int nb,
    float* __restrict__ out_bucket)
{
    extern __shared__ int sh[];
    int* hist  = sh;        // [nb]
    int* sseps = sh + nb;   // [nB]
    for (int j = threadIdx.x; j < nb; j += BLK) hist[j] = 0;
    for (int j = threadIdx.x; j < nB; j += BLK) sseps[j] = seps[j];
    __syncthreads();

    const unsigned hop = (unsigned)hop_p[0];
    const int tile = (n + G - 1) / G;
    const int beg = blockIdx.x * tile;
    const int end = min(n, beg + tile);

    for (int i = beg + threadIdx.x; i < end; i += BLK) {
        float x = coords[3 * i + 0];
        float y = coords[3 * i + 1];
        float z = coords[3 * i + 2];
        unsigned bid = 0;
        #pragma unroll 4
        for (int k = 0; k < nB; k++) bid += (sseps[k] <= i);
        unsigned b = bucket_of(x, y, z, bid, hop, (unsigned)nb);
        out_bucket[i] = (float)b;
        atomicAdd(&hist[b], 1);
    }
    __syncthreads();
    for (int j = threadIdx.x; j < nb; j += BLK)
        g_hist[(size_t)blockIdx.x * nb + j] = hist[j];
}

// Pass 2: one thread per bucket — exclusive scan over the G blocks (coalesced,
// L2-resident), emit counts (f32), zero-fill only the deficit slots.
__global__ void psh_pass2(int nb, float* __restrict__ out_counts,
                          float* __restrict__ out_coord)
{
    int j = blockIdx.x * blockDim.x + threadIdx.x;
    if (j >= nb) return;
    int carry = 0;
    #pragma unroll 4
    for (int b = 0; b < G; b++) {
        size_t idx = (size_t)b * nb + j;
        int v = g_hist[idx];
        g_hist[idx] = carry;
        carry += v;
    }
    out_counts[j] = (float)carry;
    int filled = min(carry, BUCKET_SIZE);
    float* dst = out_coord + ((size_t)j * BUCKET_SIZE + filled) * 3;
    int nz = (BUCKET_SIZE - filled) * 3;
    for (int t = 0; t < nz; t++) dst[t] = 0.0f;
}

// Pass 3: stable scatter. Rank = block-exclusive prefix (g_hist) +
// intra-block stable rank (match_any within warp; warps applied in order).
__global__ __launch_bounds__(BLK) void psh_pass3(
    const float* __restrict__ coords, const int* __restrict__ seps,
    const int* __restrict__ hop_p, int n, int nB, int nb,
    float* __restrict__ out_coord)
{
    extern __shared__ int sh[];
    int* off   = sh;        // [nb] running per-bucket counters
    int* sseps = sh + nb;   // [nB]
    for (int j = threadIdx.x; j < nb; j += BLK)
        off[j] = g_hist[(size_t)blockIdx.x * nb + j];
    for (int j = threadIdx.x; j < nB; j += BLK) sseps[j] = seps[j];
    __syncthreads();

    const unsigned hop = (unsigned)hop_p[0];
    const int tile = (n + G - 1) / G;
    const int beg = blockIdx.x * tile;
    const int end = min(n, beg + tile);
    const int warpid = threadIdx.x >> 5;
    const int lane   = threadIdx.x & 31;
    const int NW = BLK / 32;

    for (int c = beg; c < end; c += BLK) {
        int i = c + threadIdx.x;
        bool valid = (i < end);
        float x = 0.f, y = 0.f, z = 0.f;
        unsigned b = 0, mask = 0;
        int leader = 0, intra = 0, cnt = 0;

        unsigned vm = __ballot_sync(0xffffffffu, valid);
        if (valid) {
            x = coords[3 * i + 0];
            y = coords[3 * i + 1];
            z = coords[3 * i + 2];
            unsigned bid = 0;
            #pragma unroll 4
            for (int k = 0; k < nB; k++) bid += (sseps[k] <= i);
            b = bucket_of(x, y, z, bid, hop, (unsigned)nb);
            mask   = __match_any_sync(vm, b);
            leader = __ffs(mask) - 1;
            intra  = __popc(mask & ((1u << lane) - 1u));
            cnt    = __popc(mask);
        }

        int rank = BUCKET_SIZE;  // default: dropped / invalid
        // Serialize warps so the shared counters advance in warp order
        // (stability). Group leaders hit distinct buckets -> plain RMW ok.
        for (int w = 0; w < NW; w++) {
            __syncthreads();
            if (valid && warpid == w) {
                int base = 0;
                if (lane == leader) {
                    base = off[b];
                    off[b] = base + cnt;
                }
                base = __shfl_sync(mask, base, leader);
                rank = base + intra;
            }
        }
        __syncthreads();

        if (valid && rank < BUCKET_SIZE) {
            size_t s = ((size_t)b * BUCKET_SIZE + rank) * 3;
            out_coord[s + 0] = x;
            out_coord[s + 1] = y;
            out_coord[s + 2] = z;
        }
    }
}

extern "C" void kernel_launch(void* const* d_in, const int* in_sizes, int n_in,
                              void* d_out, int out_size)
{
    const float* coords = (const float*)d_in[0];
    const int*   seps   = (const int*)d_in[1];
    const int*   hop_p  = (const int*)d_in[2];

    const int n  = in_sizes[0] / 3;
    const int nB = in_sizes[1];
    const int pad_to = ((n + BUCKET_SIZE - 1) / BUCKET_SIZE) * BUCKET_SIZE;
    const int nb = pad_to / BUCKET_SIZE;

    // Output layout (flattened concat of reference tuple, promoted to f32):
    // [scattered_coord: pad_to*3][counts: nb][bucket: n]
    float* out_coord  = (float*)d_out;
    float* out_counts = out_coord + (size_t)pad_to * 3;
    float* out_bucket = out_counts + nb;

    size_t shbytes = (size_t)(nb + 64) * sizeof(int);

    psh_pass1<<<G, BLK, shbytes>>>(coords, seps, hop_p, n, nB, nb, out_bucket);
    psh_pass2<<<(nb + 255) / 256, 256>>>(nb, out_counts, out_coord);
    psh_pass3<<<G, BLK, shbytes>>>(coords, seps, hop_p, n, nB, nb, out_coord);
}

// round 2
// speedup vs baseline: 1.8176x; 1.8176x over previous
#include <cuda_runtime.h>
#include <cuda_bf16.h>
#include <stdint.h>

#define BUCKET_SIZE 512
#define G 296          // tile-blocks for pass1/pass3 (2 per SM on 148 SMs)
#define BLK1 512
#define BLK3 256       // 8 warps -> one 6-bit field per warp in a u64
#define MAXNB 8192     // actual nb = 7813

// per-(block,bucket) histogram -> exclusive offsets. 296*8192*4 = 9.7 MB (L2-resident)
__device__ int g_hist[(size_t)G * MAXNB];

// ---------------- Pass 1: bucket ids + per-block histograms ----------------
__global__ __launch_bounds__(BLK1) void psh_pass1(
    const float* __restrict__ coords, const int* __restrict__ seps,
    const int* __restrict__ hop_p, int n, int nB, int nb,
    unsigned long long magic, float* __restrict__ out_bucket)
{
    extern __shared__ int sh[];
    int* hist  = sh;        // [nb]
    int* sseps = sh + nb;   // [nB]
    for (int j = threadIdx.x; j < nb; j += BLK1) hist[j] = 0;
    for (int j = threadIdx.x; j < nB; j += BLK1) sseps[j] = seps[j];
    __syncthreads();

    const unsigned hop = (unsigned)hop_p[0];
    const int tile = (n + G - 1) / G;
    const int beg = blockIdx.x * tile;
    const int end = min(n, beg + tile);

    // bid(i) = #{k : seps[k] <= i}. Over a contiguous tile only seps in
    // (beg, end-1] vary; the rest are constant. Usually khi == klo.
    int klo = 0, khi = 0;
    for (int k = 0; k < nB; k++) {
        klo += (sseps[k] <= beg);
        khi += (sseps[k] <= end - 1);
    }

    for (int i = beg + threadIdx.x; i < end; i += BLK1) {
        float x = coords[3 * i + 0];
        float y = coords[3 * i + 1];
        float z = coords[3 * i + 2];
        unsigned bid = (unsigned)klo;
        for (int k = klo; k < khi; k++) bid += (sseps[k] <= i);
        unsigned vx = (unsigned)(int)floorf(x);
        unsigned vy = (unsigned)(int)floorf(y);
        unsigned vz = (unsigned)(int)floorf(z);
        unsigned h = vx * 73856093u ^ vy * 19349663u ^ vz * 83492791u
                   ^ bid * 2654435761u;
        h += hop;
        // exact h % nb via magic = ceil(2^64/nb)
        unsigned q = (unsigned)__umul64hi((unsigned long long)h, magic);
        unsigned b = h - q * (unsigned)nb;
        out_bucket[i] = (float)b;
        atomicAdd(&hist[b], 1);
    }
    __syncthreads();
    for (int j = threadIdx.x; j < nb; j += BLK1)
        g_hist[(size_t)blockIdx.x * nb + j] = hist[j];
}

// ------- Pass 2: warp-per-bucket exclusive scan + counts + deficit fill -------
__global__ __launch_bounds__(256) void psh_pass2(
    int nb, float* __restrict__ out_counts, float* __restrict__ out_coord)
{
    const int j = blockIdx.x * 8 + (threadIdx.x >> 5);
    const int lane = threadIdx.x & 31;
    if (j >= nb) return;

    const int S = (G + 31) / 32;  // rows per lane
    int v[S];
    int r0 = lane * S;
    int partial = 0;
    #pragma unroll
    for (int t = 0; t < S; t++) {
        int row = r0 + t;
        int val = (row < G) ? g_hist[(size_t)row * nb + j] : 0;
        v[t] = val;
        partial += val;
    }
    // warp inclusive scan of per-lane partials
    int incl = partial;
    #pragma unroll
    for (int d = 1; d < 32; d <<= 1) {
        int y = __shfl_up_sync(0xffffffffu, incl, d);
        if (lane >= d) incl += y;
    }
    int excl = incl - partial;
    int total = __shfl_sync(0xffffffffu, incl, 31);

    int run = excl;
    #pragma unroll
    for (int t = 0; t < S; t++) {
        int row = r0 + t;
        if (row < G) { g_hist[(size_t)row * nb + j] = run; run += v[t]; }
    }

    if (lane == 0) out_counts[j] = (float)total;

    // zero only the unfilled slots of this bucket (lane-parallel)
    int filled = min(total, BUCKET_SIZE);
    int nz = (BUCKET_SIZE - filled) * 3;
    float* dst = out_coord + ((size_t)j * BUCKET_SIZE + filled) * 3;
    for (int t = lane; t < nz; t += 32) dst[t] = 0.0f;
}

// ---------------- Pass 3: stable scatter (packed-u64 cross-warp rank) ----------------
__global__ __launch_bounds__(BLK3) void psh_pass3(
    const float* __restrict__ coords, const float* __restrict__ bucket_f,
    int n, int nb, float* __restrict__ out_coord)
{
    extern __shared__ int sh[];
    unsigned long long* packed = (unsigned long long*)sh;  // [nb]
    int* off = (int*)(packed + nb);                        // [nb]
    for (int j = threadIdx.x; j < nb; j += BLK3) {
        packed[j] = 0ull;
        off[j] = g_hist[(size_t)blockIdx.x * nb + j];
    }
    __syncthreads();

    const int tile = (n + G - 1) / G;
    const int beg = blockIdx.x * tile;
    const int end = min(n, beg + tile);
    const int lane   = threadIdx.x & 31;
    const int warpid = threadIdx.x >> 5;

    for (int c = beg; c < end; c += BLK3) {
        int i = c + threadIdx.x;
        bool valid = (i < end);
        float x = 0.f, y = 0.f, z = 0.f;
        unsigned b = 0, mask = 0;
        int leader = 0, intra = 0, cnt = 0;

        unsigned vm = __ballot_sync(0xffffffffu, valid);
        if (valid) {
            x = coords[3 * i + 0];
            y = coords[3 * i + 1];
            z = coords[3 * i + 2];
            b = (unsigned)bucket_f[i];          // exact: nb < 2^24
            mask   = __match_any_sync(vm, b);
            leader = __ffs(mask) - 1;
            intra  = __popc(mask & ((1u << lane) - 1u));
            cnt    = __popc(mask);              // <= 32, fits 6 bits
        }
        bool isLeader = valid && (lane == leader);

        if (isLeader)
            atomicAdd(&packed[b], (unsigned long long)cnt << (6 * warpid));
        __syncthreads();

        int bp = 0, total = 0, loww = 8;
        if (isLeader) {
            unsigned long long word = packed[b];
            int prefix = 0;
            #pragma unroll
            for (int w = 0; w < 8; w++) {
                int f = (int)((word >> (6 * w)) & 63u);
                total += f;
                if (w < warpid) prefix += f;
                if (f && loww == 8) loww = w;
            }
            bp = off[b] + prefix;  // stable base for this warp's group
        }
        __syncthreads();           // all off[b] reads done before owner writes
        if (isLeader && warpid == loww) {
            off[b] = bp + total;   // prefix==0 for the owner
            packed[b] = 0ull;
        }

        if (valid) {
            int bpg = __shfl_sync(mask, bp, leader);
            int rank = bpg + intra;
            if (rank < BUCKET_SIZE) {
                size_t s = ((size_t)b * BUCKET_SIZE + rank) * 3;
                out_coord[s + 0] = x;
                out_coord[s + 1] = y;
                out_coord[s + 2] = z;
            }
        }
        __syncthreads();           // packed[] zeroing visible before next chunk
    }
}

extern "C" void kernel_launch(void* const* d_in, const int* in_sizes, int n_in,
                              void* d_out, int out_size)
{
    const float* coords = (const float*)d_in[0];
    const int*   seps   = (const int*)d_in[1];
    const int*   hop_p  = (const int*)d_in[2];

    const int n  = in_sizes[0] / 3;
    const int nB = in_sizes[1];
    const int pad_to = ((n + BUCKET_SIZE - 1) / BUCKET_SIZE) * BUCKET_SIZE;
    const int nb = pad_to / BUCKET_SIZE;

    float* out_coord  = (float*)d_out;
    float* out_counts = out_coord + (size_t)pad_to * 3;
    float* out_bucket = out_counts + nb;

    unsigned long long magic = (~0ULL) / (unsigned)nb + 1ULL;

    size_t sh1 = (size_t)(nb + 64) * sizeof(int);
    size_t sh3 = (size_t)nb * 12 + 128;  // u64 packed + int off

    static bool attr_set = false;
    if (!attr_set) {
        cudaFuncSetAttribute(psh_pass3,
                             cudaFuncAttributeMaxDynamicSharedMemorySize,
                             (int)((size_t)MAXNB * 12 + 128));
        attr_set = true;
    }

    psh_pass1<<<G, BLK1, sh1>>>(coords, seps, hop_p, n, nB, nb, magic, out_bucket);
    psh_pass2<<<(nb + 7) / 8, 256>>>(nb, out_counts, out_coord);
    psh_pass3<<<G, BLK3, sh3>>>(coords, out_bucket, n, nb, out_coord);
}